// round 17
// baseline (speedup 1.0000x reference)
#include <cuda_runtime.h>
#include <cuda_bf16.h>

// Problem constants (fixed by the reference: pc (4,4096,3), mask (4,4096,30))
#define BQ_B 4
#define BQ_N 4096
#define BQ_C 30
#define BQ_K 16
#define BQ_R2 0.04f

#define WARPS_PER_BLOCK 8
#define NUM_QUERIES (BQ_B * BQ_N)                       // 16384
#define NUM_BLOCKS (NUM_QUERIES / WARPS_PER_BLOCK)      // 2048
#define GROUPS_PER_BATCH (BQ_N / 4)                     // 1024 4-candidate groups

// SoA: per (batch, group): X(x0..3), Y(y0..3), Z(z0..3), M(msq0..3)
// group g covers candidates 4g..4g+3; lane L of 128-block blk is group blk*32+L.
__device__ float4   g_soa[BQ_B * GROUPS_PER_BATCH * 4];
__device__ float    g_partials[NUM_BLOCKS];
__device__ unsigned g_ticket = 0;   // reset by the last block each launch

// ---- Prep: transpose pc into per-group SoA with precomputed msq ----
__global__ __launch_bounds__(256)
void ballq_prep_kernel(const float* __restrict__ pc) {
    const int g = blockIdx.x * 256 + threadIdx.x;        // 0..4095
    const int b = g >> 10;                               // batch
    const int grp = g & (GROUPS_PER_BATCH - 1);          // group in batch
    const float* __restrict__ p = pc + (size_t)b * BQ_N * 3 + (size_t)grp * 12;

    const float x0 = p[0],  y0 = p[1],  z0 = p[2];
    const float x1 = p[3],  y1 = p[4],  z1 = p[5];
    const float x2 = p[6],  y2 = p[7],  z2 = p[8];
    const float x3 = p[9],  y3 = p[10], z3 = p[11];

    // msq: identical expression to the former inline computation (bit-exact)
    const float m0 = x0 * x0 + y0 * y0 + z0 * z0;
    const float m1 = x1 * x1 + y1 * y1 + z1 * z1;
    const float m2 = x2 * x2 + y2 * y2 + z2 * z2;
    const float m3 = x3 * x3 + y3 * y3 + z3 * z3;

    float4* __restrict__ dst = g_soa + (size_t)g * 4;
    dst[0] = make_float4(x0, x1, x2, x3);
    dst[1] = make_float4(y0, y1, y2, y3);
    dst[2] = make_float4(z0, z1, z2, z3);
    dst[3] = make_float4(m0, m1, m2, m3);
}

__global__ __launch_bounds__(WARPS_PER_BLOCK * 32)
void ballq_loss_kernel(const float* __restrict__ pc,
                       const float* __restrict__ mask,
                       float* __restrict__ out) {
    const int warp = threadIdx.x >> 5;
    const int lane = threadIdx.x & 31;
    const int q = blockIdx.x * WARPS_PER_BLOCK + warp;   // query id, 0..16383
    const int b = q >> 12;                               // q / 4096
    const int n = q & (BQ_N - 1);                        // q % 4096

    const float* __restrict__ pcb = pc + (size_t)b * BQ_N * 3;

    // Query point (broadcast load, same address across warp)
    const float qx = pcb[n * 3 + 0];
    const float qy = pcb[n * 3 + 1];
    const float qz = pcb[n * 3 + 2];
    const float qsq = qx * qx + qy * qy + qz * qz;

    const unsigned lanemask_lt = (1u << lane) - 1u;

    __shared__ int sidx[WARPS_PER_BLOCK][BQ_K];

    // ---- Ball-query scan: first K indices (index order) with d2 < R2 ----
    // Lane L owns candidates base+4L..base+4L+3 via SoA (4 LDG.128, msq
    // precomputed). Emit: ballot-rank parallel writes; 3 ballots encode the
    // per-lane hit count c in binary (c&1, c&2, c==4).
    // d2 = qsq + msq - 2*dot matches the reference's algebraic form so
    // boundary rounding errors correlate with it.
    const float4* __restrict__ pl =
        g_soa + ((size_t)b * GROUPS_PER_BATCH + (size_t)lane) * 4;

    int cnt = 0;  // uniform across the warp (may exceed BQ_K transiently)
    for (int base = 0; base < BQ_N && cnt < BQ_K; base += 128, pl += 128) {
        const float4 X = pl[0];
        const float4 Y = pl[1];
        const float4 Z = pl[2];
        const float4 M = pl[3];

        unsigned nib = 0u;
        if (qsq + M.x - 2.0f * (qx * X.x + qy * Y.x + qz * Z.x) < BQ_R2) nib |= 1u;
        if (qsq + M.y - 2.0f * (qx * X.y + qy * Y.y + qz * Z.y) < BQ_R2) nib |= 2u;
        if (qsq + M.z - 2.0f * (qx * X.z + qy * Y.z + qz * Z.z) < BQ_R2) nib |= 4u;
        if (qsq + M.w - 2.0f * (qx * X.w + qy * Y.w + qz * Z.w) < BQ_R2) nib |= 8u;

        // Count-bit encoding: c = popc(nib) in 0..4 -> 3 ballots
        const int c = __popc(nib);
        const unsigned b0 = __ballot_sync(0xffffffffu, c & 1);
        const unsigned b1 = __ballot_sync(0xffffffffu, c & 2);
        const unsigned b2 = __ballot_sync(0xffffffffu, c == 4);

        const int excl = __popc(b0 & lanemask_lt)
                       + 2 * __popc(b1 & lanemask_lt)
                       + 4 * __popc(b2 & lanemask_lt);
        const int total = __popc(b0) + 2 * __popc(b1) + 4 * __popc(b2);

        // Each hit lane writes its own hits, ascending j (ascending index)
        if (nib) {
            int s = cnt + excl;
            unsigned nb = nib;
            const int bi = base + lane * 4;
            do {
                const int jj = __ffs(nb) - 1;
                if (s < BQ_K) sidx[warp][s] = bi + jj;
                s++;
                nb &= nb - 1u;
            } while (nb);
        }
        cnt += total;   // uniform
    }
    __syncwarp();
    // Pad remaining slots with the first found index (cnt >= 1: self hit)
    if (lane == 0) {
        const int f = sidx[warp][0];
        for (int j = (cnt < BQ_K ? cnt : BQ_K); j < BQ_K; j++) sidx[warp][j] = f;
    }
    __syncwarp();

    // ---- Loss: lane c handles channel c (c < 30); neighbor rows coalesced ----
    float acc = 0.0f;
    if (lane < BQ_C) {
        const float* __restrict__ mb = mask + (size_t)b * BQ_N * BQ_C;
        const float mq = mb[n * BQ_C + lane];
#pragma unroll
        for (int j = 0; j < BQ_K; j++) {
            const int id = sidx[warp][j];
            acc += fabsf(mq - mb[id * BQ_C + lane]);
        }
    }
    // Warp reduce (lanes 30,31 contribute 0)
#pragma unroll
    for (int off = 16; off; off >>= 1)
        acc += __shfl_down_sync(0xffffffffu, acc, off);

    __shared__ float wl[WARPS_PER_BLOCK];
    if (lane == 0) wl[warp] = acc;
    __syncthreads();

    // Per-block partial in fixed order (no float atomics -> deterministic)
    __shared__ bool is_last;
    if (threadIdx.x == 0) {
        float s = 0.0f;
#pragma unroll
        for (int w2 = 0; w2 < WARPS_PER_BLOCK; w2++) s += wl[w2];
        g_partials[blockIdx.x] = s;
        __threadfence();                                  // publish partial
        unsigned tk = atomicAdd(&g_ticket, 1u);           // int ticket only
        is_last = (tk == NUM_BLOCKS - 1);
    }
    __syncthreads();

    // ---- Fused final reduction: last block, fixed order, deterministic ----
    if (is_last) {
        __shared__ float sh[256];
        float s = 0.0f;
        for (int i = threadIdx.x; i < NUM_BLOCKS; i += 256)
            s += g_partials[i];
        sh[threadIdx.x] = s;
        __syncthreads();
#pragma unroll
        for (int off = 128; off; off >>= 1) {
            if (threadIdx.x < off) sh[threadIdx.x] += sh[threadIdx.x + off];
            __syncthreads();
        }
        if (threadIdx.x == 0) {
            out[0] = sh[0] * (1.0f / ((float)BQ_K * (float)NUM_QUERIES));
            g_ticket = 0;                                 // reset for next replay
        }
    }
}

extern "C" void kernel_launch(void* const* d_in, const int* in_sizes, int n_in,
                              void* d_out, int out_size) {
    const float* pc   = (const float*)d_in[0];   // (4, 4096, 3) float32
    const float* mask = (const float*)d_in[1];   // (4, 4096, 30) float32
    float* out = (float*)d_out;                  // scalar float32

    ballq_prep_kernel<<<(BQ_B * GROUPS_PER_BATCH) / 256, 256>>>(pc);
    ballq_loss_kernel<<<NUM_BLOCKS, WARPS_PER_BLOCK * 32>>>(pc, mask, out);
}